// round 13
// baseline (speedup 1.0000x reference)
#include <cuda_runtime.h>
#include <math.h>

#define VOL   262144    // 64^3
#define FW    131072    // u32 words per (b,L) field
#define NB    2
#define NL    3
#define INF16 25000     // 25000 + 63^2 = 28969 < 32767 (s16-safe)
#define INFDUP 0x61A861A8u
#define W_ANI 0.096f
#define RWIN  8         // window radius; exact when result <= (RWIN+1)^2
#define THR   81        // (RWIN+1)^2

// z-pass squared-distance field, u16 packed in u32: [(b*3+L)][z][y][x/2]
__device__ unsigned g_zf32[NB * NL * FW];   // 3 MB
__device__ double   g_acc;
__device__ unsigned g_done;

// ---------------------------------------------------------------------------
// Kernel A: per-(b,y) build column masks, scan -> z-distance^2 for all
// (L, z, x), coalesced store of the full z-field slab.
// ---------------------------------------------------------------------------
__global__ void __launch_bounds__(256)
k_zfield(const int* __restrict__ labels)
{
    __shared__ unsigned short smk[NL * 4 * 64];
    __shared__ unsigned short szf[NL * 64 * 64];   // [L][z][x], 24 KB

    const int tid = threadIdx.x;
    const int b = (int)blockIdx.x >> 6, y = (int)blockIdx.x & 63;
    const int x = tid & 63, seg = tid >> 6;

    unsigned m0 = 0, m1 = 0, m2 = 0;
    const int* lp = labels + b * VOL + seg * 16 * 4096 + y * 64 + x;
    #pragma unroll
    for (int zz = 0; zz < 16; ++zz) {
        int lab = lp[zz * 4096];
        m0 |= (lab == 0) ? (1u << zz) : 0u;
        m1 |= (lab == 1) ? (1u << zz) : 0u;
        m2 |= (lab == 2) ? (1u << zz) : 0u;
    }
    smk[(0 * 4 + seg) * 64 + x] = (unsigned short)m0;
    smk[(1 * 4 + seg) * 64 + x] = (unsigned short)m1;
    smk[(2 * 4 + seg) * 64 + x] = (unsigned short)m2;
    __syncthreads();

    if (tid < 192) {
        int L = tid >> 6, xx = tid & 63;
        unsigned long long m =
              (unsigned long long)smk[(L * 4 + 0) * 64 + xx]
            | ((unsigned long long)smk[(L * 4 + 1) * 64 + xx] << 16)
            | ((unsigned long long)smk[(L * 4 + 2) * 64 + xx] << 32)
            | ((unsigned long long)smk[(L * 4 + 3) * 64 + xx] << 48);
        int dist[64];
        int d = 127;
        #pragma unroll
        for (int z = 0; z < 64; ++z) {
            d = ((m >> z) & 1ull) ? 0 : min(d + 1, 127);
            dist[z] = d;
        }
        d = 127;
        #pragma unroll
        for (int z = 63; z >= 0; --z) {
            d = ((m >> z) & 1ull) ? 0 : min(d + 1, 127);
            int dd = min(dist[z], d);
            szf[(L * 64 + z) * 64 + xx] =
                (unsigned short)((dd > 63) ? INF16 : dd * dd);
        }
    }
    __syncthreads();

    // coalesced copy-out of the FULL slab: NL*64*64 u16 = 6144 u32 words
    const unsigned* s32 = (const unsigned*)szf;
    #pragma unroll
    for (int e = 0; e < 24; ++e) {
        int w  = e * 256 + tid;               // (L, z, xp)
        int L  = w >> 11, rem = w & 2047;
        int z  = rem >> 5, xp = rem & 31;
        g_zf32[(b * NL + L) * FW + z * 2048 + y * 32 + xp] = s32[w];
    }
}

// ---------------------------------------------------------------------------
// Single-label windowed SIMD min-plus (d^2 as compile-time dup16 immediates).
// Returns nonzero if any output > THR (window possibly inexact).
// ---------------------------------------------------------------------------
template<int PITCH>
__device__ __forceinline__ int win_minplus1(const unsigned* __restrict__ s,
                                            int lane, int i0, unsigned acc[4])
{
    #pragma unroll
    for (int k = 0; k < 4; ++k) acc[k] = 0x7FFF7FFFu;

    #pragma unroll
    for (int m = -RWIN; m <= RWIN + 3; ++m) {
        const int row = (i0 + m + 8) * PITCH + lane;
        unsigned v = s[row];
        #pragma unroll
        for (int k = 0; k < 4; ++k) {
            const int d = m - k;
            if (d < -RWIN || d > RWIN) continue;
            const unsigned q = (unsigned)(d * d) * 0x10001u;
            acc[k] = __viaddmin_s16x2(v, q, acc[k]);
        }
    }
    unsigned mx = 0;
    #pragma unroll
    for (int k = 0; k < 4; ++k) mx = __vmaxu2(mx, acc[k]);
    return ((mx & 0xFFFFu) > THR) | ((mx >> 16) > THR);
}

// ---------------------------------------------------------------------------
// Kernel B: block = (b, z-plane t, y-half) x 768 threads = three 256-thread
// LABEL GROUPS working the same half-plane (3x warp parallelism vs R12).
// ---------------------------------------------------------------------------
__global__ void __launch_bounds__(768, 2)
k_main(const float* __restrict__ x, const int* __restrict__ y,
       float* __restrict__ out)
{
    __shared__ unsigned sv[NL][48 * 33];   // z-vals rows y0-8..y0+39; reused as res
    __shared__ unsigned sw[NL][80 * 17];   // y-result transposed (x rows -8..71)
    __shared__ float    dtlut[THR + 1];
    __shared__ float    wsum[24];

    const int tid = threadIdx.x;
    const int Lg  = tid >> 8;              // label group 0..2
    const int lt  = tid & 255;             // thread within group
    const int bid = (int)blockIdx.x;
    const int b   = bid >> 7;
    const int t   = (bid & 127) >> 1;
    const int y0  = (bid & 1) * 32;

    if (tid <= THR) dtlut[tid] = fmaf(W_ANI, sqrtf((float)tid), 1.0f);

    // ---- group Lg loads its own z-val tile rows y0-8 .. y0+39
    const unsigned* zf = &g_zf32[(b * NL + Lg) * FW + t * 2048];
    #pragma unroll
    for (int e = 0; e < 6; ++e) {
        int widx = e * 256 + lt;               // 0..1535
        int r = widx >> 5, xp = widx & 31;
        int ygl = y0 - 8 + r;
        unsigned word = INFDUP;
        if ((unsigned)ygl < 64u) word = zf[ygl * 32 + xp];
        sv[Lg][r * 33 + xp] = word;
    }
    // sw guard rows (x = -8..-1, 64..71): 272 words per label
    #pragma unroll
    for (int w = lt; w < 272; w += 256) {
        int rr = w / 17, c = w - rr * 17;
        int row = (rr < 8) ? rr : (rr + 64);
        sw[Lg][row * 17 + c] = INFDUP;
    }
    __syncthreads();

    unsigned acc[4];

    // ================= y-minplus (scan y, lines = x) =================
    const int cp = lt & 31;
    const int i0 = (lt >> 5) * 4;
    int bad = win_minplus1<33>(sv[Lg], cp, i0, acc);
    const int fb1 = __syncthreads_or(bad);
    if (fb1) {
        // exact fallback from the global z-field (cold path)
        #pragma unroll
        for (int k = 0; k < 4; ++k) acc[k] = 0x7FFF7FFFu;
        for (int j = 0; j < 64; ++j) {
            unsigned vj = zf[j * 32 + cp];
            #pragma unroll
            for (int k = 0; k < 4; ++k) {
                int d = j - (y0 + i0 + k);
                unsigned q = (unsigned)(d * d) * 0x10001u;
                acc[k] = __viaddmin_s16x2(vj, q, acc[k]);
            }
        }
    }
    // clamp + transposed write into sw
    {
        unsigned short* sw16 = (unsigned short*)sw[Lg];
        #pragma unroll
        for (int k = 0; k < 4; ++k) {
            unsigned a = __vminu2(acc[k], INFDUP);
            sw16[(2 * cp + 8) * 34 + (i0 + k)] = (unsigned short)(a & 0xFFFFu);
            sw16[(2 * cp + 9) * 34 + (i0 + k)] = (unsigned short)(a >> 16);
        }
    }
    __syncthreads();

    // ================= x-minplus (scan x, lines = y) =================
    const int cp2 = lt & 15;
    const int j0  = (lt >> 4) * 4;
    bad = win_minplus1<17>(sw[Lg], cp2, j0, acc);
    const int fb2 = __syncthreads_or(bad);
    if (fb2) {
        #pragma unroll
        for (int k = 0; k < 4; ++k) acc[k] = 0x7FFF7FFFu;
        for (int j = 0; j < 64; ++j) {
            unsigned vj = sw[Lg][(j + 8) * 17 + cp2];
            #pragma unroll
            for (int k = 0; k < 4; ++k) {
                int d = j - (j0 + k);
                unsigned q = (unsigned)(d * d) * 0x10001u;
                acc[k] = __viaddmin_s16x2(vj, q, acc[k]);
            }
        }
    }
    // result res16[ylocal*66 + x] (reuse sv[Lg])
    {
        unsigned short* res16 = (unsigned short*)sv[Lg];
        #pragma unroll
        for (int k = 0; k < 4; ++k) {
            res16[(2 * cp2)     * 66 + (j0 + k)] = (unsigned short)(acc[k] & 0xFFFFu);
            res16[(2 * cp2 + 1) * 66 + (j0 + k)] = (unsigned short)(acc[k] >> 16);
        }
    }
    __syncthreads();

    // ---- fused reduce over the half-plane (2048 voxels, 768 threads)
    const unsigned short* r0 = (const unsigned short*)sv[0];
    const unsigned short* r1 = (const unsigned short*)sv[1];
    const unsigned short* r2 = (const unsigned short*)sv[2];
    const bool exact = !(fb1 | fb2);
    const int gbase = b * VOL + t * 4096 + y0 * 64;
    float local = 0.0f;
    #pragma unroll
    for (int e = 0; e < 3; ++e) {
        int v = e * 768 + tid;
        if (v < 2048) {
            int lab  = y[gbase + v];
            float x1 = x[(b * NL + 1) * VOL + t * 4096 + y0 * 64 + v];
            float x2 = x[(b * NL + 2) * VOL + t * 4096 + y0 * 64 + v];
            int yy = v >> 6, xx = v & 63;
            int n0 = r0[yy * 66 + xx];
            int n1 = r1[yy * 66 + xx];
            int n2 = r2[yy * 66 + xx];
            int m = min(lab == 0 ? 0x7FFF : n0,
                    min(lab == 1 ? 0x7FFF : n1,
                        lab == 2 ? 0x7FFF : n2));
            float dt = exact ? dtlut[m]
                             : fmaf(W_ANI, sqrtf((float)m), 1.0f);
            float s  = ((lab == 1) ? (1.0f - x1) : x1)
                     + ((lab == 2) ? (1.0f - x2) : x2);
            local += s * dt;
        }
    }

    #pragma unroll
    for (int o = 16; o; o >>= 1)
        local += __shfl_xor_sync(0xFFFFFFFFu, local, o);
    if ((tid & 31) == 0) wsum[tid >> 5] = local;
    __syncthreads();

    if (tid == 0) {
        float s = 0.0f;
        #pragma unroll
        for (int i = 0; i < 24; ++i) s += wsum[i];
        atomicAdd(&g_acc, (double)s);
        __threadfence();
        unsigned old = atomicAdd(&g_done, 1u);
        if (old == gridDim.x - 1) {            // last block: finalize + reset
            double tot = atomicAdd(&g_acc, 0.0);
            out[0] = (float)(tot / (double)(NB * 2 * VOL) + 1e-5);
            g_acc  = 0.0;
            g_done = 0u;
            __threadfence();
        }
    }
}

// ---------------------------------------------------------------------------
extern "C" void kernel_launch(void* const* d_in, const int* in_sizes, int n_in,
                              void* d_out, int out_size)
{
    const float* x = (const float*)d_in[0];   // (2,3,64,64,64) f32
    const int*   y = (const int*)  d_in[1];   // (2,1,64,64,64) i32
    float* out = (float*)d_out;

    k_zfield<<<NB * 64, 256>>>(y);
    k_main  <<<NB * 128, 768>>>(x, y, out);
}